// round 13
// baseline (speedup 1.0000x reference)
#include <cuda_runtime.h>

// Spline_74354473828848 — KAN B-spline layer, uniform cubic spline fast path.
// out[b,o,i] = sum_{r=0..3} w_r(x[b,i]) * coeff[o, i, j(x[b,i]) + r]
//
// Round 13: o-slice-resident CTAs. CTA = (8 o-values, 16 batches). The
// coeff slice for 8 consecutive o is one contiguous 38KB block -> flat
// coalesced load into smem (per-i stride 153 = odd mod 32). Weights are
// precomputed once per (b,i) into smem. Inner loop: LDS.128 weights +
// 4 smem gathers (29-cyc latency vs 234 L2) + direct coalesced scalar STG
// (lanes = consecutive i). No transpose kernel, no staging tile, 1 launch.

#define BATCH   1024
#define IN_DIM  64
#define OUT_DIM 64
#define N_COEF  19
#define O_TILE  8
#define B_TILE  16
#define THREADS 256

#define I_STRIDE   (N_COEF * O_TILE + 1)        // 153 words, odd mod 32
#define CS_WORDS   (IN_DIM * I_STRIDE)          // 9792
#define SLICE_FLTS (O_TILE * IN_DIM * N_COEF)   // 9728, contiguous in coeff
#define NW         (B_TILE * IN_DIM)            // 1024 weight sets
// dynamic smem: cs | sw(float4) | sa(int)
#define SMEM_BYTES (CS_WORDS * 4 + NW * 16 + NW * 4)   // 59648

__global__ __launch_bounds__(THREADS, 3)
void spline_kernel(const float* __restrict__ x,
                   const float* __restrict__ coeff,
                   float* __restrict__ out)
{
    extern __shared__ float smem[];
    float*  cs = smem;                              // [i][g*8+ol], stride 153
    float4* sw = (float4*)(smem + CS_WORDS);        // weights per (b,i)
    int*    sa = (int*)(smem + CS_WORDS + NW * 4);  // gather base per (b,i)

    const int bg = blockIdx.x >> 3;     // batch group 0..63
    const int og = blockIdx.x & 7;      // o group 0..7
    const int b0 = bg * B_TILE;
    const int o0 = og * O_TILE;
    const int t  = threadIdx.x;

    // ---- load coeff slice for o0..o0+7: one contiguous 38KB block ----
    const float* base = coeff + (size_t)o0 * (IN_DIM * N_COEF);
    #pragma unroll
    for (int idx = t; idx < SLICE_FLTS; idx += THREADS) {
        float v  = base[idx];
        int   ol = idx / (IN_DIM * N_COEF);
        int   r  = idx - ol * (IN_DIM * N_COEF);
        int   i  = r / N_COEF;
        int   g  = r - i * N_COEF;
        cs[i * I_STRIDE + g * O_TILE + ol] = v;
    }

    // ---- precompute weights + gather offsets for all (b,i) of this tile ----
    #pragma unroll
    for (int k = t; k < NW; k += THREADS) {
        int   b  = k >> 6;
        int   i  = k & 63;
        float xv = x[(b0 + b) * IN_DIM + i];     // coalesced
        float sc = xv * 16.0f;                   // knots dyadic: exact
        int   j  = (int)sc;
        j = max(0, min(j, 15));
        float u  = sc - (float)j;
        float um = 1.0f - u;
        float u2 = u * u, u3 = u2 * u;
        const float c6 = 1.0f / 6.0f;
        sw[k] = make_float4(um * um * um * c6,
                            (3.0f * u3 - 6.0f * u2 + 4.0f) * c6,
                            (-3.0f * u3 + 3.0f * u2 + 3.0f * u + 1.0f) * c6,
                            u3 * c6);
        sa[k] = i * I_STRIDE + j * O_TILE;
    }
    __syncthreads();

    // ---- main loop: all outputs of this (o-tile, batch-tile) ----
    const int ol   = t >> 5;            // 0..7, this thread's o
    const int lane = t & 31;
    const size_t orow0 = ((size_t)b0 * OUT_DIM + o0 + ol) * IN_DIM;

    #pragma unroll
    for (int b = 0; b < B_TILE; ++b) {
        #pragma unroll
        for (int half = 0; half < 2; ++half) {
            int i = lane + 32 * half;
            int k = (b << 6) + i;
            float4 w = sw[k];           // LDS.128, conflict-free phases
            int    a = sa[k] + ol;
            float acc = w.x * cs[a + 0 * O_TILE]
                      + w.y * cs[a + 1 * O_TILE]
                      + w.z * cs[a + 2 * O_TILE]
                      + w.w * cs[a + 3 * O_TILE];
            // 32 lanes -> consecutive i: 128B coalesced STG
            out[orow0 + (size_t)b * (OUT_DIM * IN_DIM) + i] = acc;
        }
    }
}

extern "C" void kernel_launch(void* const* d_in, const int* in_sizes, int n_in,
                              void* d_out, int out_size)
{
    const float* x     = (const float*)d_in[0];
    const float* coeff = (const float*)d_in[1];
    // d_in[2] = grid (uniform, encoded analytically) — unused
    float* out = (float*)d_out;

    static int configured = 0;
    if (!configured) {
        cudaFuncSetAttribute(spline_kernel,
                             cudaFuncAttributeMaxDynamicSharedMemorySize,
                             SMEM_BYTES);
        configured = 1;
    }

    dim3 grid((BATCH / B_TILE) * (OUT_DIM / O_TILE));   // 64*8 = 512
    spline_kernel<<<grid, THREADS, SMEM_BYTES>>>(x, coeff, out);
}

// round 16
// speedup vs baseline: 1.4865x; 1.4865x over previous
#include <cuda_runtime.h>

// Spline_74354473828848 — KAN B-spline layer, uniform cubic spline fast path.
// out[b,o,i] = sum_{r=0..3} w_r(x[b,i]) * coeff[o, i, j(x[b,i]) + r]
//
// Round 16: exact R8 main body (measured best main: 9.79us; scalar STS into
// pad-65 s[o][i], all accesses 4B-aligned) + PDL transpose overlap (measured
// ~-0.6us overhead). The STS.128 staging experiment (R14/15) is abandoned:
// its alignment fix forces 8-way writeback bank conflicts.

#define BATCH   1024
#define IN_DIM  64
#define OUT_DIM 64
#define N_COEF  19
#define CT_ELEMS (IN_DIM * N_COEF * OUT_DIM)   // 77824

__device__ float g_ct[CT_ELEMS];               // [i][g][o], 311 KB scratch

// ---- kernel 1: coeff[o][i][g] -> CT[i][g][o] ----
__global__ __launch_bounds__(256)
void transpose_kernel(const float* __restrict__ coeff)
{
    int q = blockIdx.x * blockDim.x + threadIdx.x;   // quad index, exact fit
    int o4 = q & 15;
    int g  = (q >> 4) % N_COEF;
    int i  = q / (16 * N_COEF);

    const int o = 4 * o4;
    float4 v;
    v.x = coeff[((o + 0) * IN_DIM + i) * N_COEF + g];
    v.y = coeff[((o + 1) * IN_DIM + i) * N_COEF + g];
    v.z = coeff[((o + 2) * IN_DIM + i) * N_COEF + g];
    v.w = coeff[((o + 3) * IN_DIM + i) * N_COEF + g];
    ((float4*)g_ct)[q] = v;

    cudaTriggerProgrammaticLaunchCompletion();
}

// ---- kernel 2: main contraction, one CTA (256 thr) per batch ----
__global__ __launch_bounds__(256)
void spline_main(const float* __restrict__ x, float* __restrict__ out)
{
    __shared__ float s[OUT_DIM][IN_DIM + 1];   // [o][i], pad 65 (4B aligned)

    const int b  = blockIdx.x;
    const int t  = threadIdx.x;
    const int w  = t >> 5;          // warp 0..7
    const int l  = t & 31;
    const int h  = l >> 4;          // half-warp 0/1
    const int o4 = l & 15;          // lane owns o = 4*o4 .. 4*o4+3

    // Prologue independent of CT (overlaps transpose via PDL).
    float xv[4];
    #pragma unroll
    for (int p = 0; p < 4; ++p)
        xv[p] = x[b * IN_DIM + 16 * p + 2 * w + h];

    cudaGridDependencySynchronize();

    #pragma unroll
    for (int p = 0; p < 4; ++p) {
        const int i = 16 * p + 2 * w + h;   // 0..63

        // closed-form uniform cubic B-spline weights (exact interval select)
        float sc = xv[p] * 16.0f;           // knots dyadic: exact
        int   j  = (int)sc;
        j = max(0, min(j, 15));
        float u  = sc - (float)j;
        float um = 1.0f - u;
        float u2 = u * u, u3 = u2 * u;
        const float c6 = 1.0f / 6.0f;
        float w0 = um * um * um * c6;
        float w1 = (3.0f * u3 - 6.0f * u2 + 4.0f) * c6;
        float w2 = (-3.0f * u3 + 3.0f * u2 + 3.0f * u + 1.0f) * c6;
        float w3 = u3 * c6;

        // 4 coalesced LDG.128: rows j..j+3 of CT[i], this lane's o-quad
        const float4* base =
            (const float4*)(g_ct + ((size_t)i * N_COEF + j) * OUT_DIM) + o4;
        float4 v0 = base[0 * (OUT_DIM / 4)];
        float4 v1 = base[1 * (OUT_DIM / 4)];
        float4 v2 = base[2 * (OUT_DIM / 4)];
        float4 v3 = base[3 * (OUT_DIM / 4)];

        s[4 * o4 + 0][i] = w0 * v0.x + w1 * v1.x + w2 * v2.x + w3 * v3.x;
        s[4 * o4 + 1][i] = w0 * v0.y + w1 * v1.y + w2 * v2.y + w3 * v3.y;
        s[4 * o4 + 2][i] = w0 * v0.z + w1 * v1.z + w2 * v2.z + w3 * v3.z;
        s[4 * o4 + 3][i] = w0 * v0.w + w1 * v1.w + w2 * v2.w + w3 * v3.w;
    }
    __syncthreads();

    // Writeback: 4 x STG.128, fully coalesced 16KB slab.
    float* ob = out + (size_t)b * (OUT_DIM * IN_DIM);
    #pragma unroll
    for (int k = 0; k < 4; ++k) {
        int q = k * 256 + t;        // quad index 0..1023
        int o = q >> 4;             // 0..63
        int m = q & 15;             // i-quad 0..15
        float4 vv = make_float4(s[o][4 * m + 0], s[o][4 * m + 1],
                                s[o][4 * m + 2], s[o][4 * m + 3]);
        *(float4*)(ob + o * IN_DIM + 4 * m) = vv;
    }
}

extern "C" void kernel_launch(void* const* d_in, const int* in_sizes, int n_in,
                              void* d_out, int out_size)
{
    const float* x     = (const float*)d_in[0];
    const float* coeff = (const float*)d_in[1];
    // d_in[2] = grid (uniform, encoded analytically) — unused
    float* out = (float*)d_out;

    transpose_kernel<<<CT_ELEMS / 4 / 256, 256>>>(coeff);   // 76 CTAs, exact

    cudaLaunchConfig_t cfg = {};
    cfg.gridDim  = dim3(BATCH);
    cfg.blockDim = dim3(256);
    cfg.dynamicSmemBytes = 0;
    cfg.stream = 0;
    cudaLaunchAttribute attrs[1];
    attrs[0].id = cudaLaunchAttributeProgrammaticStreamSerialization;
    attrs[0].val.programmaticStreamSerializationAllowed = 1;
    cfg.attrs = attrs;
    cfg.numAttrs = 1;
    cudaLaunchKernelEx(&cfg, spline_main, x, out);
}